// round 17
// baseline (speedup 1.0000x reference)
#include <cuda_runtime.h>
#include <math.h>
#include <stdint.h>

#define NN 262144
#define DD 16
#define KK 64
#define TAUF 0.1f
#define DLOG2PI 1.8378770664093454835
#define L2E 1.4426950408889634f
#define LN2 0.6931471805599453f

#define TPB 128            // 4 warps
#define RPB 256            // rows per block (warp: 4 tiles of 16 rows)
#define ZGRID (NN / RPB)   // 1024

// ---------------- device globals ----------------
__device__ float g_sumlogpi;
__device__ unsigned g_minkey[DD] = {
    0xFFFFFFFFu,0xFFFFFFFFu,0xFFFFFFFFu,0xFFFFFFFFu,0xFFFFFFFFu,0xFFFFFFFFu,0xFFFFFFFFu,0xFFFFFFFFu,
    0xFFFFFFFFu,0xFFFFFFFFu,0xFFFFFFFFu,0xFFFFFFFFu,0xFFFFFFFFu,0xFFFFFFFFu,0xFFFFFFFFu,0xFFFFFFFFu};
__device__ unsigned g_maxkey[DD] = {0,0,0,0,0,0,0,0,0,0,0,0,0,0,0,0};
__device__ float g_partial[ZGRID];
__device__ unsigned g_ctr = 0;

// ---------------- helpers ----------------
__device__ __forceinline__ unsigned fkey(float f) {
    unsigned u = __float_as_uint(f);
    return (u & 0x80000000u) ? ~u : (u | 0x80000000u);
}
__device__ __forceinline__ float fdec(unsigned k) {
    unsigned u = (k & 0x80000000u) ? (k & 0x7FFFFFFFu) : ~k;
    return __uint_as_float(u);
}
__device__ __forceinline__ float ex2f(float x) {
    float y; asm("ex2.approx.f32 %0, %1;" : "=f"(y) : "f"(x)); return y;
}
__device__ __forceinline__ float lg2f(float x) {
    float y; asm("lg2.approx.f32 %0, %1;" : "=f"(y) : "f"(x)); return y;
}
__device__ __forceinline__ unsigned cvt_tf32(float f) {
    unsigned u; asm("cvt.rna.tf32.f32 %0, %1;" : "=r"(u) : "f"(f)); return u;
}
__device__ __forceinline__ void mma_tf32(float& d0, float& d1, float& d2, float& d3,
                                         unsigned a0, unsigned a1, unsigned a2, unsigned a3,
                                         unsigned b0, unsigned b1) {
    asm("mma.sync.aligned.m16n8k8.row.col.f32.tf32.tf32.f32 "
        "{%0,%1,%2,%3}, {%4,%5,%6,%7}, {%8,%9}, {%0,%1,%2,%3};"
        : "+f"(d0), "+f"(d1), "+f"(d2), "+f"(d3)
        : "r"(a0), "r"(a1), "r"(a2), "r"(a3), "r"(b0), "r"(b1));
}

// ---------------- single fused kernel (tensor-core logN) ----------------
__global__ void __launch_bounds__(TPB, 4) zloss_kernel(const float* __restrict__ met,
                                                       const float* __restrict__ z,
                                                       const float* __restrict__ mu,
                                                       const float* __restrict__ pi,
                                                       const float* __restrict__ rv,
                                                       const float* __restrict__ lambda_mu,
                                                       const float* __restrict__ bv,
                                                       const float* __restrict__ Cv,
                                                       float* __restrict__ out) {
    __shared__ __align__(16) unsigned sWt[DD * KK];   // tf32 weights, [d][k]   4 KB
    __shared__ __align__(8) float sA2[KK];
    __shared__ __align__(8) float sC2[KK];
    __shared__ __align__(8) float sLP[KK];
    __shared__ float sxs[RPB];
    __shared__ float spi[KK];
    __shared__ float slse;
    __shared__ float sred[4];
    __shared__ float smn[4][DD], smx[4][DD];
    __shared__ unsigned s_last;

    const int t = threadIdx.x;
    const int lane = t & 31;
    const int wid = t >> 5;
    const int tig = lane & 3;      // threadID_in_group
    const int g = lane >> 2;       // groupID
    const int blockRow = blockIdx.x * RPB;

    // ---- prep: softmax(pi) ----
    if (t < KK) spi[t] = pi[t];
    __syncthreads();
    if (t < 32) {
        float a = spi[t], b2 = spi[t + 32];
        float m = fmaxf(a, b2);
#pragma unroll
        for (int off = 16; off; off >>= 1)
            m = fmaxf(m, __shfl_xor_sync(0xffffffffu, m, off));
        float es = __expf(a - m) + __expf(b2 - m);
        float sp = a + b2;
#pragma unroll
        for (int off = 16; off; off >>= 1) {
            es += __shfl_xor_sync(0xffffffffu, es, off);
            sp += __shfl_xor_sync(0xffffffffu, sp, off);
        }
        float lse = m + __logf(es);
        if (t == 0) {
            slse = lse;
            if (blockIdx.x == 0) g_sumlogpi = sp - 64.f * lse;
        }
    }
    __syncthreads();

    // ---- prep: per-k constants (transposed tf32 weight table) ----
    if (t < KK) {
        sLP[t] = (spi[t] - slse) * L2E;
        float rk = rv[t];
        float ie = __expf(-rk);
        float sc = L2E * ie;
        const float4* mu4 = reinterpret_cast<const float4*>(mu + t * DD);
        float msq = 0.f;
#pragma unroll
        for (int q = 0; q < 4; q++) {
            float4 mq = mu4[q];
            msq = fmaf(mq.x, mq.x, msq); msq = fmaf(mq.y, mq.y, msq);
            msq = fmaf(mq.z, mq.z, msq); msq = fmaf(mq.w, mq.w, msq);
            sWt[(4 * q + 0) * KK + t] = cvt_tf32(sc * mq.x);
            sWt[(4 * q + 1) * KK + t] = cvt_tf32(sc * mq.y);
            sWt[(4 * q + 2) * KK + t] = cvt_tf32(sc * mq.z);
            sWt[(4 * q + 3) * KK + t] = cvt_tf32(sc * mq.w);
        }
        float alpha = -0.5f * ie;
        float beta  = -0.5f * 16.f * (rk + (float)DLOG2PI);
        sA2[t] = L2E * alpha;
        sC2[t] = L2E * fmaf(alpha, msq, beta);
    }

    // ---- prologue: xs per row + per-dim min/max (x regs die here) ----
    {
        const int rowA = blockRow + t;
        const int rowB = rowA + TPB;
        const float4* xpa = reinterpret_cast<const float4*>(met + (size_t)rowA * DD);
        const float4* xpb = reinterpret_cast<const float4*>(met + (size_t)rowB * DD);
        float4 a0 = xpa[0], a1 = xpa[1], a2 = xpa[2], a3 = xpa[3];
        float4 b0 = xpb[0], b1 = xpb[1], b2 = xpb[2], b3 = xpb[3];
        float xA[DD] = { a0.x, a0.y, a0.z, a0.w, a1.x, a1.y, a1.z, a1.w,
                         a2.x, a2.y, a2.z, a2.w, a3.x, a3.y, a3.z, a3.w };
        float xB[DD] = { b0.x, b0.y, b0.z, b0.w, b1.x, b1.y, b1.z, b1.w,
                         b2.x, b2.y, b2.z, b2.w, b3.x, b3.y, b3.z, b3.w };
        float xsa = 0.f, xsb = 0.f;
#pragma unroll
        for (int d = 0; d < DD; d++) {
            xsa = fmaf(xA[d], xA[d], xsa);
            xsb = fmaf(xB[d], xB[d], xsb);
        }
        sxs[t] = xsa;
        sxs[t + TPB] = xsb;
#pragma unroll
        for (int d = 0; d < DD; d += 2) {
            float mn0 = fminf(xA[d], xB[d]),         mx0 = fmaxf(xA[d], xB[d]);
            float mn1 = fminf(xA[d + 1], xB[d + 1]), mx1 = fmaxf(xA[d + 1], xB[d + 1]);
#pragma unroll
            for (int off = 16; off; off >>= 1) {
                mn0 = fminf(mn0, __shfl_xor_sync(0xffffffffu, mn0, off));
                mx0 = fmaxf(mx0, __shfl_xor_sync(0xffffffffu, mx0, off));
                mn1 = fminf(mn1, __shfl_xor_sync(0xffffffffu, mn1, off));
                mx1 = fmaxf(mx1, __shfl_xor_sync(0xffffffffu, mx1, off));
            }
            if (lane == 0) {
                smn[wid][d] = mn0;     smx[wid][d] = mx0;
                smn[wid][d + 1] = mn1; smx[wid][d + 1] = mx1;
            }
        }
    }
    __syncthreads();

    if (t < DD) {
        float mn = fminf(fminf(smn[0][t], smn[1][t]), fminf(smn[2][t], smn[3][t]));
        atomicMin(&g_minkey[t], fkey(mn));
    } else if (t < 2 * DD) {
        int d = t - DD;
        float mx = fmaxf(fmaxf(smx[0][d], smx[1][d]), fmaxf(smx[2][d], smx[3][d]));
        atomicMax(&g_maxkey[d], fkey(mx));
    }

    // ---- B fragments: resident, per warp ----
    unsigned Bf[8][2][2];
#pragma unroll
    for (int nt = 0; nt < 8; nt++) {
#pragma unroll
        for (int kt = 0; kt < 2; kt++) {
            Bf[nt][kt][0] = sWt[(8 * kt + tig) * KK + 8 * nt + g];
            Bf[nt][kt][1] = sWt[(8 * kt + tig + 4) * KK + 8 * nt + g];
        }
    }

    // ---- main: 4 tiles of 16 rows per warp ----
    float accT = 0.f;
#pragma unroll 1
    for (int tile = 0; tile < 4; tile++) {
        const int rg = blockRow + wid * 64 + tile * 16 + g;
        const int rh = rg + 8;
        const float* xg = met + (size_t)rg * DD;
        const float* xh = met + (size_t)rh * DD;

        unsigned Ah[8], Al[8];
#pragma unroll
        for (int kt = 0; kt < 2; kt++) {
            float f0 = xg[8 * kt + tig];
            float f1 = xh[8 * kt + tig];
            float f2 = xg[8 * kt + tig + 4];
            float f3 = xh[8 * kt + tig + 4];
            unsigned h0 = cvt_tf32(f0), h1 = cvt_tf32(f1), h2 = cvt_tf32(f2), h3 = cvt_tf32(f3);
            Ah[kt * 4 + 0] = h0; Al[kt * 4 + 0] = cvt_tf32(f0 - __uint_as_float(h0));
            Ah[kt * 4 + 1] = h1; Al[kt * 4 + 1] = cvt_tf32(f1 - __uint_as_float(h1));
            Ah[kt * 4 + 2] = h2; Al[kt * 4 + 2] = cvt_tf32(f2 - __uint_as_float(h2));
            Ah[kt * 4 + 3] = h3; Al[kt * 4 + 3] = cvt_tf32(f3 - __uint_as_float(h3));
        }
        const float xsg = sxs[rg - blockRow];
        const float xsh = sxs[rh - blockRow];

        float mvg = -3.0e38f, evg = 0.f, ezg = 0.f, eug = 0.f, szg = 0.f;
        float mvh = -3.0e38f, evh = 0.f, ezh = 0.f, euh = 0.f, szh = 0.f;

        const float* zgp = z + (size_t)rg * KK + 2 * tig;
        const float* zhp = z + (size_t)rh * KK + 2 * tig;

#pragma unroll 4
        for (int nt = 0; nt < 8; nt++) {
            float2 zA = *reinterpret_cast<const float2*>(zgp + 8 * nt);
            float2 zB = *reinterpret_cast<const float2*>(zhp + 8 * nt);
            float zc0 = zA.x * L2E, zc1 = zA.y * L2E;
            float zc2 = zB.x * L2E, zc3 = zB.y * L2E;
            float d0 = zc0, d1 = zc1, d2 = zc2, d3 = zc3;
            mma_tf32(d0, d1, d2, d3, Ah[0], Ah[1], Ah[2], Ah[3], Bf[nt][0][0], Bf[nt][0][1]);
            mma_tf32(d0, d1, d2, d3, Al[0], Al[1], Al[2], Al[3], Bf[nt][0][0], Bf[nt][0][1]);
            mma_tf32(d0, d1, d2, d3, Ah[4], Ah[5], Ah[6], Ah[7], Bf[nt][1][0], Bf[nt][1][1]);
            mma_tf32(d0, d1, d2, d3, Al[4], Al[5], Al[6], Al[7], Bf[nt][1][0], Bf[nt][1][1]);

            const int kc = 8 * nt + 2 * tig;
            float2 A2p = *reinterpret_cast<const float2*>(&sA2[kc]);
            float2 C2p = *reinterpret_cast<const float2*>(&sC2[kc]);
            float2 LPp = *reinterpret_cast<const float2*>(&sLP[kc]);

            float v0 = d0 + fmaf(A2p.x, xsg, C2p.x);
            float v1 = d1 + fmaf(A2p.y, xsg, C2p.y);
            float v2 = d2 + fmaf(A2p.x, xsh, C2p.x);
            float v3 = d3 + fmaf(A2p.y, xsh, C2p.y);

            ezg += ex2f(zc0) + ex2f(zc1);
            ezh += ex2f(zc2) + ex2f(zc3);
            eug += ex2f(fmaf(-TAUF, zc0, LPp.x)) + ex2f(fmaf(-TAUF, zc1, LPp.y));
            euh += ex2f(fmaf(-TAUF, zc2, LPp.x)) + ex2f(fmaf(-TAUF, zc3, LPp.y));
            szg += zc0 + zc1;
            szh += zc2 + zc3;

            float mng = fmaxf(mvg, fmaxf(v0, v1));
            evg = fmaf(evg, ex2f(mvg - mng), ex2f(v0 - mng) + ex2f(v1 - mng));
            mvg = mng;
            float mnh = fmaxf(mvh, fmaxf(v2, v3));
            evh = fmaf(evh, ex2f(mvh - mnh), ex2f(v2 - mnh) + ex2f(v3 - mnh));
            mvh = mnh;
        }

        // combine across the 4-lane group (tig dimension)
#pragma unroll
        for (int off = 1; off <= 2; off <<= 1) {
            ezg += __shfl_xor_sync(0xffffffffu, ezg, off);
            ezh += __shfl_xor_sync(0xffffffffu, ezh, off);
            eug += __shfl_xor_sync(0xffffffffu, eug, off);
            euh += __shfl_xor_sync(0xffffffffu, euh, off);
            szg += __shfl_xor_sync(0xffffffffu, szg, off);
            szh += __shfl_xor_sync(0xffffffffu, szh, off);
            float omg = __shfl_xor_sync(0xffffffffu, mvg, off);
            float oeg = __shfl_xor_sync(0xffffffffu, evg, off);
            float mng = fmaxf(mvg, omg);
            evg = fmaf(evg, ex2f(mvg - mng), oeg * ex2f(omg - mng));
            mvg = mng;
            float omh = __shfl_xor_sync(0xffffffffu, mvh, off);
            float oeh = __shfl_xor_sync(0xffffffffu, evh, off);
            float mnh = fmaxf(mvh, omh);
            evh = fmaf(evh, ex2f(mvh - mnh), oeh * ex2f(omh - mnh));
            mvh = mnh;
        }

        if (tig == 0) {
            accT += LN2 * (fmaf(63.f, lg2f(ezg), fmaf(-64.f, lg2f(eug), mvg + lg2f(evg)))
                           - (TAUF + 1.f) * szg);
            accT += LN2 * (fmaf(63.f, lg2f(ezh), fmaf(-64.f, lg2f(euh), mvh + lg2f(evh)))
                           - (TAUF + 1.f) * szh);
        }
    }

    // ---- block reduce accT ----
#pragma unroll
    for (int off = 16; off; off >>= 1)
        accT += __shfl_xor_sync(0xffffffffu, accT, off);
    if (lane == 0) sred[wid] = accT;
    __syncthreads();

    if (t == 0) {
        g_partial[blockIdx.x] = sred[0] + sred[1] + sred[2] + sred[3];
        __threadfence();
        unsigned old = atomicAdd(&g_ctr, 1u);
        s_last = (old == (unsigned)(ZGRID - 1)) ? 1u : 0u;
    }
    __syncthreads();
    if (!s_last) return;

    // ================= last block: final scalar epilogue =================
    __threadfence();
    float* shR = spi;                      // reuse
    if (t < DD) shR[t] = fdec(g_maxkey[t]) - fdec(g_minkey[t]);
    __syncthreads();

    double R2 = 0.0;
#pragma unroll
    for (int d = 0; d < DD; d++) R2 += (double)shR[d] * (double)shR[d];
    const double cc = 5.0, gg = 4.0;
    const double Gd = cc / (50.0 * gg) * sqrt(R2);
    const double lgG = (double)__logf((float)Gd);

    const double LG_HALF = 0.5723649429247001;       // lgamma(0.5)
    const double LG_C    = 3.1780538303479458;       // lgamma(5)
    const double LG_G    = 1.791759469228055;        // lgamma(4)
    const double LG_64   = 201.00931639928152;       // lgamma(64)
    const double LN_HALF = -0.6931471805599453;
    const double LN_TENTH = -2.302585092994046;

    double acc = 0.0;
    for (int i = t; i < KK * DD; i += TPB) {
        int d = i & (DD - 1);
        float lam = lambda_mu[d];
        float var = lam * lam * shR[d];
        float diff = mu[i] - bv[i];
        float bb = bv[i];
        acc += (double)(0.5f * diff * diff / var) + (double)(0.5f * bb * bb);
    }
    for (int d = t; d < DD; d += TPB) {
        float lam = lambda_mu[d];
        float var = lam * lam * shR[d];
        acc += 0.5 * (double)KK * (double)__logf(var);
        acc -= 0.5 * LN_HALF - LG_HALF - 0.5 * (double)lam - 0.5 * (double)__expf(lam);
    }
    for (int k = t; k < KK; k += TPB) {
        float rk = rv[k], Ck = Cv[k];
        acc -= cc * (double)__logf(Ck) - (cc - 1.0) * (double)rk
               - (double)Ck * (double)__expf(-rk) - LG_C;
        acc -= gg * lgG - (gg - 1.0) * (double)Ck
               - Gd * (double)__expf(-Ck) - LG_G;
    }
    const float4* p4 = reinterpret_cast<const float4*>(g_partial);
    for (int i = t; i < ZGRID / 4; i += TPB) {
        float4 v = p4[i];
        acc -= (double)v.x + (double)v.y + (double)v.z + (double)v.w;
    }

    double* dred = reinterpret_cast<double*>(sWt);   // overlay (sWt no longer needed)
    dred[t] = acc;
    __syncthreads();
#pragma unroll
    for (int s = 64; s; s >>= 1) {
        if (t < s) dred[t] += dred[t + s];
        __syncthreads();
    }
    if (t == 0) {
        double total = dred[0];
        double sumlp = (double)g_sumlogpi;
        double G0 = LG_64 + 63.0 * LN_TENTH + sumlp;          // per-row constant in con
        total -= (double)NN * G0;                             // z-loss constant part
        total += (63.0 / 64.0) * sumlp;                       // pi_loss
        total += (double)KK * 0.5 * (double)DD * DLOG2PI;     // mu_loss const
        total += 0.5 * (double)KK * (double)DD * DLOG2PI;     // b_loss const
        out[0] = (float)total;
        atomicExch(&g_ctr, 0u);                               // reset for graph replay
    }
}

// ---------------- launch ----------------
extern "C" void kernel_launch(void* const* d_in, const int* in_sizes, int n_in,
                              void* d_out, int out_size) {
    const float* met = (const float*)d_in[0];
    const float* mu  = (const float*)d_in[1];
    const float* pi  = (const float*)d_in[2];
    const float* lam = (const float*)d_in[3];
    const float* b   = (const float*)d_in[4];
    const float* C   = (const float*)d_in[5];
    const float* r   = (const float*)d_in[6];
    const float* z   = (const float*)d_in[7];
    (void)in_sizes; (void)n_in; (void)out_size;

    zloss_kernel<<<ZGRID, TPB>>>(met, z, mu, pi, r, lam, b, C, (float*)d_out);
}